// round 10
// baseline (speedup 1.0000x reference)
#include <cuda_runtime.h>

#define NROWS 128
#define LEN   2048
#define NK    6
#define NT    256
#define NWARP (NT / 32)
#define SEGW  384                 // window-starts per segment
#define SEGP  6                   // segments per row
#define NB    (NROWS * SEGP)      // 768 blocks
#define FIXSCALE 1099511627776.0f // 2^40
#define CNT_ONE  (1ull << 54)
#define SUM_MASK (CNT_ONE - 1ull)

// bits [54..63]: completed-block count; bits [0..53]: fixed-point (2^-40) loss sum.
__device__ unsigned long long g_accum = 0ull;

__device__ __forceinline__ float4 f4add(float4 a, float4 b) {
    return make_float4(a.x + b.x, a.y + b.y, a.z + b.z, a.w + b.w);
}

__global__ void __launch_bounds__(NT, 2) entropy_fused(
    const float* __restrict__ in, const float* __restrict__ tg, float* __restrict__ out)
{
    // Local prefix over this segment's 512 reachable elements:
    // P[i] = sum over elements [base, base+i) of (e^a, a e^a, e^b, b e^b).
    __shared__ float4 P[2 * NT + 1];
    __shared__ float4 wtot[NWARP];
    __shared__ float  redk[NWARP];

    const int tid  = threadIdx.x;
    const int lane = tid & 31, wid = tid >> 5;
    const int bid  = blockIdx.x;
    const int row  = bid / SEGP;
    const int base = (bid - row * SEGP) * SEGW;    // segment start (mult of 384)

    // ---- 2 consecutive elements per thread, guarded past row end ----
    const int e0 = base + 2 * tid;
    float2 a2 = make_float2(0.f, 0.f), b2 = make_float2(0.f, 0.f);
    if (e0 < LEN) {          // e0 even -> e0+1 < LEN too
        a2 = *(const float2*)(in + (size_t)row * LEN + e0);
        b2 = *(const float2*)(tg + (size_t)row * LEN + e0);
    }
    float ea0 = __expf(a2.x), ea1 = __expf(a2.y);
    float eb0 = __expf(b2.x), eb1 = __expf(b2.y);
    if (e0 >= LEN) { ea0 = ea1 = eb0 = eb1 = 0.f; a2.x = a2.y = b2.x = b2.y = 0.f; }
    float4 v0 = make_float4(ea0, a2.x * ea0, eb0, b2.x * eb0);
    float4 v1 = f4add(make_float4(ea1, a2.y * ea1, eb1, b2.y * eb1), v0);

    // warp inclusive scan of per-thread totals
    float4 t = v1;
    #pragma unroll
    for (int off = 1; off < 32; off <<= 1) {
        float4 n;
        n.x = __shfl_up_sync(0xffffffffu, t.x, off);
        n.y = __shfl_up_sync(0xffffffffu, t.y, off);
        n.z = __shfl_up_sync(0xffffffffu, t.z, off);
        n.w = __shfl_up_sync(0xffffffffu, t.w, off);
        if (lane >= off) t = f4add(t, n);
    }
    if (lane == 31) wtot[wid] = t;
    __syncthreads();

    // every warp redundantly scans the 8 warp totals (no extra barrier)
    float4 woff;
    {
        float4 w = (lane < NWARP) ? wtot[lane] : make_float4(0.f, 0.f, 0.f, 0.f);
        #pragma unroll
        for (int off = 1; off < NWARP; off <<= 1) {
            float4 n;
            n.x = __shfl_up_sync(0xffffffffu, w.x, off);
            n.y = __shfl_up_sync(0xffffffffu, w.y, off);
            n.z = __shfl_up_sync(0xffffffffu, w.z, off);
            n.w = __shfl_up_sync(0xffffffffu, w.w, off);
            if (lane >= off && lane < NWARP) w = f4add(w, n);
        }
        const int src = (wid > 0) ? wid - 1 : 0;
        woff.x = __shfl_sync(0xffffffffu, w.x, src);
        woff.y = __shfl_sync(0xffffffffu, w.y, src);
        woff.z = __shfl_sync(0xffffffffu, w.z, src);
        woff.w = __shfl_sync(0xffffffffu, w.w, src);
        if (wid == 0) woff = make_float4(0.f, 0.f, 0.f, 0.f);
    }
    {
        float4 ex = make_float4(woff.x + t.x - v1.x, woff.y + t.y - v1.y,
                                woff.z + t.z - v1.z, woff.w + t.w - v1.w);
        P[2 * tid + 1] = f4add(v0, ex);
        P[2 * tid + 2] = f4add(v1, ex);
        if (tid == 0) P[0] = make_float4(0.f, 0.f, 0.f, 0.f);
    }
    __syncthreads();

    // ---- windows: segment covers starts [base, base+384); local prefix index s-base ----
    // ent1 - ent2 = (S1*Z2 - S2*Z1)*r - log(Z1^2 * r), r = 1/(Z1*Z2)
    const float4 lo0 = P[tid];
    const float4 lo1 = P[tid + NT];
    float acc = 0.0f;
    #pragma unroll
    for (int kk = 0; kk < NK; kk++) {
        const int   k  = 4 << kk;
        const int   nW = LEN - k + 1;
        const float wk = 1.0f / (128.0f * (float)nW);
        float acck = 0.0f;
        if (base + tid < nW) {                       // s_loc = tid
            float4 hi = P[tid + k];
            float z1 = hi.x - lo0.x, f1 = hi.y - lo0.y;
            float z2 = hi.z - lo0.z, f2 = hi.w - lo0.w;
            float r = __fdividef(1.0f, z1 * z2);
            float d = fmaf(f1 * z2 - f2 * z1, r, -__logf(z1 * z1 * r));
            acck = fabsf(d);
        }
        if (tid < SEGW - NT && base + NT + tid < nW) {  // s_loc = tid + 256 (<384)
            float4 hi = P[tid + NT + k];
            float z1 = hi.x - lo1.x, f1 = hi.y - lo1.y;
            float z2 = hi.z - lo1.z, f2 = hi.w - lo1.w;
            float r = __fdividef(1.0f, z1 * z2);
            float d = fmaf(f1 * z2 - f2 * z1, r, -__logf(z1 * z1 * r));
            acck += fabsf(d);
        }
        acc = fmaf(acck, wk, acc);
    }

    // ---- block reduce ----
    #pragma unroll
    for (int off = 16; off; off >>= 1) acc += __shfl_down_sync(0xffffffffu, acc, off);
    if (lane == 0) redk[wid] = acc;
    __syncthreads();
    if (tid == 0) {
        float s = 0.0f;
        #pragma unroll
        for (int w = 0; w < NWARP; w++) s += redk[w];
        // single fixed-point atomic: order-invariant integer sum -> deterministic
        unsigned long long add = CNT_ONE + (unsigned long long)__float2ll_rn(s * FIXSCALE);
        unsigned long long old = atomicAdd(&g_accum, add);
        if ((old >> 54) == NB - 1) {                 // final arrival
            unsigned long long tot = (old + add) & SUM_MASK;
            out[0] = (float)((double)tot * (1.0 / 1099511627776.0));
            g_accum = 0ull;                          // reset for next graph replay
        }
    }
}

extern "C" void kernel_launch(void* const* d_in, const int* in_sizes, int n_in,
                              void* d_out, int out_size) {
    const float* in = (const float*)d_in[0];
    const float* tg = (const float*)d_in[1];
    entropy_fused<<<NB, NT>>>(in, tg, (float*)d_out);
}

// round 11
// speedup vs baseline: 1.0369x; 1.0369x over previous
#include <cuda_runtime.h>

#define NROWS 128
#define LEN   2048
#define NK    6
#define NT    128                 // 4 warps per block
#define WSTART 128                // window-starts per warp
#define NB    512                 // 128 rows x 4 blocks (16 warps/row)
#define PITCH 289                 // slot(256)=288 -> 289 float4 per warp slice
#define FIXSCALE 1099511627776.0f // 2^40
#define CNT_ONE  (1ull << 54)
#define SUM_MASK (CNT_ONE - 1ull)

// bits [54..63]: completed-block count; bits [0..53]: fixed-point (2^-40) loss sum.
__device__ unsigned long long g_accum = 0ull;

// pad one float4 per 8 entries: both scan stores and window reads hit the
// 4-phase LDS.128/STS.128 minimum.
#define SLOT(i) ((i) + ((i) >> 3))

__device__ __forceinline__ float4 f4add(float4 a, float4 b) {
    return make_float4(a.x + b.x, a.y + b.y, a.z + b.z, a.w + b.w);
}

__global__ void __launch_bounds__(NT, 4) entropy_fused(
    const float* __restrict__ in, const float* __restrict__ tg, float* __restrict__ out)
{
    __shared__ float4 Psh[4 * PITCH];   // per-warp private prefix slices
    __shared__ float  redk[4];

    const int tid  = threadIdx.x;
    const int lane = tid & 31, w = tid >> 5;
    const int row  = blockIdx.x >> 2;
    const int S    = ((blockIdx.x & 3) << 9) + (w << 7);   // warp's first window-start

    // ---- load 8 consecutive elements per lane (2 float4 per tensor), guarded ----
    const float* xi = in + (size_t)row * LEN;
    const float* xt = tg + (size_t)row * LEN;
    const int e = S + 8 * lane;                  // max 1920+248 = 2168
    float4 A0 = make_float4(0.f,0.f,0.f,0.f), A1 = A0, B0 = A0, B1 = A0;
    if (e < LEN)     { A0 = *(const float4*)(xi + e);     B0 = *(const float4*)(xt + e); }
    if (e + 4 < LEN) { A1 = *(const float4*)(xi + e + 4); B1 = *(const float4*)(xt + e + 4); }
    const float ax[8] = {A0.x,A0.y,A0.z,A0.w,A1.x,A1.y,A1.z,A1.w};
    const float bx[8] = {B0.x,B0.y,B0.z,B0.w,B1.x,B1.y,B1.z,B1.w};

    // ---- register-local inclusive prefix of (e^a, a e^a, e^b, b e^b) ----
    float4 v[8];
    {
        float4 run = make_float4(0.f,0.f,0.f,0.f);
        #pragma unroll
        for (int j = 0; j < 8; j++) {
            float ea = __expf(ax[j]);
            float eb = __expf(bx[j]);
            run.x += ea;  run.y += ax[j] * ea;
            run.z += eb;  run.w += bx[j] * eb;
            v[j] = run;
        }
    }

    // ---- warp-only scan of per-lane totals (no block barrier anywhere) ----
    float4 t = v[7];
    #pragma unroll
    for (int off = 1; off < 32; off <<= 1) {
        float4 n;
        n.x = __shfl_up_sync(0xffffffffu, t.x, off);
        n.y = __shfl_up_sync(0xffffffffu, t.y, off);
        n.z = __shfl_up_sync(0xffffffffu, t.z, off);
        n.w = __shfl_up_sync(0xffffffffu, t.w, off);
        if (lane >= off) t = f4add(t, n);
    }
    const float4 ex = make_float4(t.x - v[7].x, t.y - v[7].y,
                                  t.z - v[7].z, t.w - v[7].w);

    // ---- write local prefix (entries 1..256) into this warp's smem slice ----
    float4* Pw = Psh + w * PITCH;
    #pragma unroll
    for (int j = 0; j < 8; j++) {
        int idx = 8 * lane + j + 1;
        Pw[SLOT(idx)] = f4add(v[j], ex);
    }
    if (lane == 0) Pw[0] = make_float4(0.f,0.f,0.f,0.f);
    __syncwarp();

    // ---- windows: starts S + lane + 32j, j=0..3, for all 6 k ----
    // ent1 - ent2 = (S1*Z2 - S2*Z1)*r - log(Z1^2 * r), r = 1/(Z1*Z2)
    float4 lo[4];
    #pragma unroll
    for (int j = 0; j < 4; j++) {
        int sl = lane + 32 * j;
        lo[j] = Pw[SLOT(sl)];
    }
    float acc = 0.0f;
    #pragma unroll
    for (int kk = 0; kk < NK; kk++) {
        const int   k  = 4 << kk;
        const int   nW = LEN - k + 1;
        const float wk = 1.0f / (128.0f * (float)nW);
        float acck = 0.0f;
        #pragma unroll
        for (int j = 0; j < 4; j++) {
            const int sl = lane + 32 * j;
            if (S + sl < nW) {
                float4 hi = Pw[SLOT(sl + k)];
                float z1 = hi.x - lo[j].x, f1 = hi.y - lo[j].y;
                float z2 = hi.z - lo[j].z, f2 = hi.w - lo[j].w;
                float r = __fdividef(1.0f, z1 * z2);
                float d = fmaf(f1 * z2 - f2 * z1, r, -__logf(z1 * z1 * r));
                acck += fabsf(d);
            }
        }
        acc = fmaf(acck, wk, acc);
    }

    // ---- warp reduce, then tiny 4-warp block reduce ----
    #pragma unroll
    for (int off = 16; off; off >>= 1) acc += __shfl_down_sync(0xffffffffu, acc, off);
    if (lane == 0) redk[w] = acc;
    __syncthreads();
    if (tid == 0) {
        float s = redk[0] + redk[1] + redk[2] + redk[3];
        // single fixed-point atomic: order-invariant integer sum -> deterministic
        unsigned long long add = CNT_ONE + (unsigned long long)__float2ll_rn(s * FIXSCALE);
        unsigned long long old = atomicAdd(&g_accum, add);
        if ((old >> 54) == NB - 1) {                 // final arrival
            unsigned long long tot = (old + add) & SUM_MASK;
            out[0] = (float)((double)tot * (1.0 / 1099511627776.0));
            g_accum = 0ull;                          // reset for next graph replay
        }
    }
}

extern "C" void kernel_launch(void* const* d_in, const int* in_sizes, int n_in,
                              void* d_out, int out_size) {
    const float* in = (const float*)d_in[0];
    const float* tg = (const float*)d_in[1];
    entropy_fused<<<NB, NT>>>(in, tg, (float*)d_out);
}